// round 15
// baseline (speedup 1.0000x reference)
#include <cuda_runtime.h>
#include <cuda_bf16.h>
#include <cstdint>

// ---------------- problem constants ----------------
#define INS   224
#define NH    220
#define NB    48400
#define ICH   16
#define OCH   64
#define KTOT  400
#define XSZ   (ICH*INS*INS)      // 802816

#define OUT_OFF_W   (OCH*NB)
#define OUT_OFF_EXP (OUT_OFF_W + OCH*KTOT)

#define MB2   110                // bands (2 image rows each)
#define NG    5                  // reduce stage-1 groups (22 bands each)
#define YROW  49280              // g_yh per-oc size: 220 rows x 224 (pad 4 = 0)

// ---------------- scratch ----------------
__device__ __nv_bfloat16 g_xh[XSZ];
__device__ __nv_bfloat16 g_xl[XSZ];
__device__ __nv_bfloat16 g_xhs[XSZ];         // bf16(x[e+1])
__device__ __nv_bfloat16 g_xls[XSZ];         // lo(x[e+1])
__device__ uint32_t g_xq_h[XSZ];             // pack(hi x[e], hi x[e+220])
__device__ uint32_t g_xq_l[XSZ];
__device__ uint32_t g_xr_h[XSZ];             // pack(hi x[e], hi x[e+49276])
__device__ uint32_t g_xr_l[XSZ];
__device__ __nv_bfloat16 g_Wh[OCH * KTOT];
__device__ __nv_bfloat16 g_Wl[OCH * KTOT];
__device__ __nv_bfloat16 g_yh[OCH * YROW];
__device__ float g_Cpart[MB2 * 512 * OCH];   // 14.4MB
__device__ float g_ytypart[MB2 * OCH * OCH];
__device__ float g_colpart[MB2 * OCH];
__device__ float g_Cred[NG * 512 * OCH];
__device__ float g_ytyred[NG * OCH * OCH];
__device__ float g_Cfin[512 * OCH];
__device__ float g_ytyF[OCH * OCH];
__device__ float g_gfp[OCH];

#define MMA16816(c, a0,a1,a2,a3, b0,b1) \
  asm volatile("mma.sync.aligned.m16n8k16.row.col.f32.bf16.bf16.f32 " \
    "{%0,%1,%2,%3},{%4,%5,%6,%7},{%8,%9},{%0,%1,%2,%3};" \
    : "+f"((c)[0]),"+f"((c)[1]),"+f"((c)[2]),"+f"((c)[3]) \
    : "r"(a0),"r"(a1),"r"(a2),"r"(a3),"r"(b0),"r"(b1))

#define LDSM4(r0,r1,r2,r3, saddr) \
  asm volatile("ldmatrix.sync.aligned.m8n8.x4.shared.b16 {%0,%1,%2,%3}, [%4];" \
    : "=r"(r0),"=r"(r1),"=r"(r2),"=r"(r3) : "r"(saddr))

#define CP_ASYNC4(saddr, gptr) \
  asm volatile("cp.async.ca.shared.global [%0], [%1], 4;" \
    :: "r"(saddr), "l"(gptr) : "memory")
#define CP_COMMIT()   asm volatile("cp.async.commit_group;" ::: "memory")
#define CP_WAIT_ALL() asm volatile("cp.async.wait_group 0;" ::: "memory")

__device__ __forceinline__ uint32_t smem_u32(const void* p) {
    return (uint32_t)__cvta_generic_to_shared(p);
}
__device__ __forceinline__ uint32_t pack_bf2(__nv_bfloat16 lo, __nv_bfloat16 hi) {
    unsigned short a = *(unsigned short*)&lo, b = *(unsigned short*)&hi;
    return (uint32_t)a | ((uint32_t)b << 16);
}

// ======================================================================
// K0a: x -> all bf16 pair arrays
// ======================================================================
__global__ void k_cvt_x(const float* __restrict__ x)
{
    int e = blockIdx.x * 256 + threadIdx.x;
    if (e >= XSZ) return;
    float v = x[e];
    __nv_bfloat16 h = __float2bfloat16(v);
    __nv_bfloat16 l = __float2bfloat16(v - __bfloat162float(h));
    g_xh[e] = h; g_xl[e] = l;

    float v1 = (e + 1 < XSZ) ? x[e + 1] : 0.f;
    __nv_bfloat16 h1 = __float2bfloat16(v1);
    g_xhs[e] = h1;
    g_xls[e] = __float2bfloat16(v1 - __bfloat162float(h1));

    float vq = (e + 220 < XSZ) ? x[e + 220] : 0.f;
    __nv_bfloat16 hq = __float2bfloat16(vq);
    __nv_bfloat16 lq = __float2bfloat16(vq - __bfloat162float(hq));
    g_xq_h[e] = pack_bf2(h, hq);
    g_xq_l[e] = pack_bf2(l, lq);

    float vr = (e + 49276 < XSZ) ? x[e + 49276] : 0.f;
    __nv_bfloat16 hr = __float2bfloat16(vr);
    __nv_bfloat16 lr = __float2bfloat16(vr - __bfloat162float(hr));
    g_xr_h[e] = pack_bf2(h, hr);
    g_xr_l[e] = pack_bf2(l, lr);
}

// ======================================================================
// K0b: W -> bf16 hi/lo ; zero g_yh row pads
// ======================================================================
__global__ void k_cvt_w(const float* __restrict__ W)
{
    int idx = blockIdx.x * 256 + threadIdx.x;
    if (idx < OCH * KTOT) {
        float v = W[idx];
        __nv_bfloat16 h = __float2bfloat16(v);
        g_Wh[idx] = h;
        g_Wl[idx] = __float2bfloat16(v - __bfloat162float(h));
    } else if (idx < OCH * KTOT + OCH * 220 * 2) {
        int p = idx - OCH * KTOT;
        int oc = p / 440, rem = p - oc * 440;
        int r = rem >> 1, half = rem & 1;
        uint32_t* yh32 = (uint32_t*)g_yh;
        yh32[((oc * YROW + r * 224 + 220) >> 1) + half] = 0u;
    }
}

// ======================================================================
// A pair-load for conv: element pair (kb, kb+1) at pixel column eb(+8).
// ======================================================================
__device__ __forceinline__ void loadpairs(int kb, int eb, int pxA,
    uint32_t& h0, uint32_t& h1, uint32_t& l0, uint32_t& l1)
{
    int q = kb / 5;
    int kj = kb - q * 5;
    int ic = q / 5;
    int e = q * 224 + ic * 49056 + eb + kj;
    if (kj == 4) {
        bool icx = (q - ic * 5) == 4;
        const uint32_t* ph = icx ? g_xr_h : g_xq_h;
        const uint32_t* pl = icx ? g_xr_l : g_xq_l;
        h0 = ph[e]; h1 = ph[e + 8];
        l0 = pl[e]; l1 = pl[e + 8];
    } else {
        int par = (pxA + kj) & 1;
        const uint32_t* ph = par ? (const uint32_t*)g_xhs : (const uint32_t*)g_xh;
        const uint32_t* pl = par ? (const uint32_t*)g_xls : (const uint32_t*)g_xl;
        int w0 = e >> 1;
        h0 = ph[w0]; h1 = ph[w0 + 4];
        l0 = pl[w0]; l1 = pl[w0 + 4];
    }
}

// ======================================================================
// K1: conv + inhibition (R14 verbatim). grid (2, 220), 224 thr.
// ======================================================================
#define WPITCH 20
#define WBUF   (64 * WPITCH)

__global__ void __launch_bounds__(224, 4)
k_conv_mma(float* __restrict__ dout)
{
    __shared__ uint32_t wsh[2 * WBUF];
    __shared__ uint32_t wsl[2 * WBUF];

    const int tid = threadIdx.x;
    const int w = tid >> 5, lane = tid & 31;
    const int g = lane >> 2, t = lane & 3;
    const int h = blockIdx.x;
    const int i = blockIdx.y;
    const int J0 = h * 108;
    const int pxA = (w << 4) + g;
    const int eb = i * 224 + J0 + pxA;

    const int nrow_off = ((lane >> 4) & 1) * 8 + (lane & 7);
    const int k_off = ((lane >> 3) & 1) * 4;
    const uint32_t wsh_s = smem_u32(wsh);
    const uint32_t wsl_s = smem_u32(wsl);
    const uint32_t* wh2g = (const uint32_t*)g_Wh;
    const uint32_t* wl2g = (const uint32_t*)g_Wl;

    float c[8][4];
#pragma unroll
    for (int nt = 0; nt < 8; nt++)
#pragma unroll
        for (int q = 0; q < 4; q++) c[nt][q] = 0.f;

    auto fillW = [&](int s, int buf) {
        const int nu = (s < 12) ? 16 : 8;
        const int base = s * 16;
        for (int idx = tid; idx < 64 * nu; idx += 224) {
            int row, u;
            if (nu == 16) { row = idx >> 4; u = idx & 15; }
            else          { row = idx >> 3; u = idx & 7;  }
            uint32_t so = (uint32_t)(buf * WBUF + row * WPITCH + u) * 4;
            CP_ASYNC4(wsh_s + so, wh2g + row * 200 + base + u);
            CP_ASYNC4(wsl_s + so, wl2g + row * 200 + base + u);
        }
    };

    fillW(0, 0);
    CP_COMMIT();

    for (int s = 0; s < 13; s++) {
        CP_WAIT_ALL();
        __syncthreads();
        if (s < 12) { fillW(s + 1, (s + 1) & 1); CP_COMMIT(); }

        const int k0s = s * 32;
        const int nks = (s < 12) ? 2 : 1;
        const uint32_t bufoff = (uint32_t)((s & 1) * WBUF) * 4;

        for (int ksl = 0; ksl < nks; ksl++) {
            const int kb0 = k0s + ksl * 16 + 2 * t;
            uint32_t ah0, ah1, al0, al1, ah2, ah3, al2, al3;
            loadpairs(kb0,     eb, pxA, ah0, ah1, al0, al1);
            loadpairs(kb0 + 8, eb, pxA, ah2, ah3, al2, al3);

            const uint32_t wbase = bufoff +
                ((uint32_t)(nrow_off * WPITCH + ksl * 8 + k_off)) * 4;
#pragma unroll
            for (int p = 0; p < 4; p++) {
                uint32_t bh0, bh1, bh2, bh3, bl0, bl1, bl2, bl3;
                const uint32_t off = wbase + (uint32_t)(p * 16 * WPITCH) * 4;
                LDSM4(bh0, bh1, bh2, bh3, wsh_s + off);
                LDSM4(bl0, bl1, bl2, bl3, wsl_s + off);
                MMA16816(c[2 * p],     ah0, ah1, ah2, ah3, bh0, bh1);
                MMA16816(c[2 * p],     al0, al1, al2, al3, bh0, bh1);
                MMA16816(c[2 * p],     ah0, ah1, ah2, ah3, bl0, bl1);
                MMA16816(c[2 * p + 1], ah0, ah1, ah2, ah3, bh2, bh3);
                MMA16816(c[2 * p + 1], al0, al1, al2, al3, bh2, bh3);
                MMA16816(c[2 * p + 1], ah0, ah1, ah2, ah3, bl2, bl3);
            }
        }
        __syncthreads();
    }

    // ---- inhibition + writeback ----
    float m0 = 0.f, m1 = 0.f;
#pragma unroll
    for (int nt = 0; nt < 8; nt++) {
        m0 = fmaxf(m0, fmaxf(c[nt][0], c[nt][1]));
        m1 = fmaxf(m1, fmaxf(c[nt][2], c[nt][3]));
    }
    m0 = fmaxf(m0, __shfl_xor_sync(0xFFFFFFFFu, m0, 1));
    m0 = fmaxf(m0, __shfl_xor_sync(0xFFFFFFFFu, m0, 2));
    m1 = fmaxf(m1, __shfl_xor_sync(0xFFFFFFFFu, m1, 1));
    m1 = fmaxf(m1, __shfl_xor_sync(0xFFFFFFFFu, m1, 2));
    const float inv0 = 1.f / (m0 + 1e-9f);
    const float inv1 = 1.f / (m1 + 1e-9f);

    const int pxg = i * NH + J0 + pxA;
    const int pyg = i * 224 + J0 + pxA;
#pragma unroll
    for (int nt = 0; nt < 8; nt++) {
        const int oc = nt * 8 + 2 * t;
        float v;
        v = fmaxf(c[nt][0], 0.f) * inv0; v = (v * v) * (v * v) * v;
        dout[(size_t)oc * NB + pxg] = v;
        g_yh[(size_t)oc * YROW + pyg] = __float2bfloat16(v);
        v = fmaxf(c[nt][1], 0.f) * inv0; v = (v * v) * (v * v) * v;
        dout[(size_t)(oc + 1) * NB + pxg] = v;
        g_yh[(size_t)(oc + 1) * YROW + pyg] = __float2bfloat16(v);
        v = fmaxf(c[nt][2], 0.f) * inv1; v = (v * v) * (v * v) * v;
        dout[(size_t)oc * NB + pxg + 8] = v;
        g_yh[(size_t)oc * YROW + pyg + 8] = __float2bfloat16(v);
        v = fmaxf(c[nt][3], 0.f) * inv1; v = (v * v) * (v * v) * v;
        dout[(size_t)(oc + 1) * NB + pxg + 8] = v;
        g_yh[(size_t)(oc + 1) * YROW + pyg + 8] = __float2bfloat16(v);
    }
}

// ======================================================================
// K2a: y^T @ y + colsums. grid 110, 256 thr, no smem.
// ======================================================================
__global__ void __launch_bounds__(256)
k_yty_mma()
{
    const int tid  = threadIdx.x;
    const int band = blockIdx.x;
    const int w    = tid >> 5;
    const int lane = tid & 31;
    const int g    = lane >> 2;
    const int t    = lane & 3;
    const int m0 = (w & 3) * 16;
    const int n0 = (w >> 2) * 32;

    const uint32_t* yh32 = (const uint32_t*)g_yh;

    float c[4][4];
#pragma unroll
    for (int n = 0; n < 4; n++)
#pragma unroll
        for (int q = 0; q < 4; q++) c[n][q] = 0.f;

#pragma unroll
    for (int b2 = 0; b2 < 2; b2++) {
        const int ir = band * 2 + b2;
        const uint32_t rowoff = (uint32_t)(ir * 112);
        const uint32_t baA = (uint32_t)((m0 + g) * YROW >> 1) + rowoff;
        const uint32_t baB = (uint32_t)((m0 + g + 8) * YROW >> 1) + rowoff;
#pragma unroll 2
        for (int ks = 0; ks < 14; ks++) {
            uint32_t a0 = yh32[baA + ks * 8 + t];
            uint32_t a2 = yh32[baA + ks * 8 + t + 4];
            uint32_t a1 = yh32[baB + ks * 8 + t];
            uint32_t a3 = yh32[baB + ks * 8 + t + 4];
#pragma unroll
            for (int nt = 0; nt < 4; nt++) {
                const int n = n0 + nt * 8 + g;
                uint32_t bb = (uint32_t)(n * YROW >> 1) + rowoff;
                uint32_t b0 = yh32[bb + ks * 8 + t];
                uint32_t b1 = yh32[bb + ks * 8 + t + 4];
                MMA16816(c[nt], a0, a1, a2, a3, b0, b1);
            }
        }
    }

    float* dst = g_ytypart + (size_t)band * 4096;
#pragma unroll
    for (int nt = 0; nt < 4; nt++) {
        const int col = n0 + nt * 8 + 2 * t;
        *(float2*)&dst[(m0 + g) * 64 + col]     = make_float2(c[nt][0], c[nt][1]);
        *(float2*)&dst[(m0 + g + 8) * 64 + col] = make_float2(c[nt][2], c[nt][3]);
    }

    {
        const int oc = tid >> 2, q = tid & 3;
        float s = 0.f;
#pragma unroll
        for (int b2 = 0; b2 < 2; b2++) {
            const uint32_t base = (uint32_t)(oc * YROW >> 1) +
                                  (uint32_t)((band * 2 + b2) * 112) + q * 28;
#pragma unroll 7
            for (int k = 0; k < 28; k++) {
                uint32_t v = yh32[base + k];
                __nv_bfloat162 hh = *(__nv_bfloat162*)&v;
                float2 f = __bfloat1622float2(hh);
                s += f.x + f.y;
            }
        }
        s += __shfl_xor_sync(0xFFFFFFFFu, s, 1);
        s += __shfl_xor_sync(0xFFFFFFFFu, s, 2);
        if (q == 0) g_colpart[band * OCH + oc] = s;
    }
}

// ======================================================================
// K2b: y^T @ xf. grid (110, 4) = 440 blocks (one wave at 3/SM),
// 256 thr, 59.4KB dyn smem, cp.async double-buffered B.
// ======================================================================
#define BPITCH 116
#define BSZ    (64 * BPITCH)       // 7424 u32 per buffer

extern __shared__ uint32_t s_B[];  // 2 * BSZ

__global__ void __launch_bounds__(256, 3)
k_ytxf_mma()
{
    const int tid  = threadIdx.x;
    const int band = blockIdx.x;     // rows 2*band, 2*band+1
    const int kt   = blockIdx.y;
    const int w    = tid >> 5;
    const int lane = tid & 31;
    const int g    = lane >> 2;
    const int t    = lane & 3;

    const uint32_t* yh32 = (const uint32_t*)g_yh;
    const uint32_t* xh32  = (const uint32_t*)g_xh;
    const uint32_t* xhs32 = (const uint32_t*)g_xhs;

    int rA = kt * 128 + w * 16 + g;
    int rB = rA + 8;
    int rc0 = 0, rc1 = 0;
    const uint32_t *p0 = xh32, *p1 = xh32;
    if (rA < KTOT) {
        int ic = rA / 25, rem = rA - ic * 25;
        int ki = rem / 5, kj = rem - ki * 5;
        rc0 = ic * 50176 + ki * 224 + kj;
        if (kj & 1) p0 = xhs32;
    }
    if (rB < KTOT) {
        int ic = rB / 25, rem = rB - ic * 25;
        int ki = rem / 5, kj = rem - ki * 5;
        rc1 = ic * 50176 + ki * 224 + kj;
        if (kj & 1) p1 = xhs32;
    }

    const uint32_t bsm = smem_u32(s_B);
    const int nrow_off = ((lane >> 4) & 1) * 8 + (lane & 7);
    const int k_off = ((lane >> 3) & 1) * 4;

    // zero the pad words of both buffers
    {
        int buf = tid >> 7, rem = tid & 127;
        int row = rem >> 1, p = rem & 1;
        s_B[buf * BSZ + row * BPITCH + 110 + p] = 0u;
    }

    auto fillB = [&](int ir, int buf) {
        for (int idx = tid; idx < 64 * 112; idx += 256) {
            int row = idx / 112, pc = idx - row * 112;
            if (pc < 110) {
                uint32_t so = (uint32_t)(buf * BSZ + row * BPITCH + pc) * 4;
                CP_ASYNC4(bsm + so, yh32 + ((row * YROW + ir * 224) >> 1) + pc);
            }
        }
    };

    float c[8][4];
#pragma unroll
    for (int n = 0; n < 8; n++)
#pragma unroll
        for (int q = 0; q < 4; q++) c[n][q] = 0.f;

    fillB(band * 2, 0);
    CP_COMMIT();

#pragma unroll
    for (int b2 = 0; b2 < 2; b2++) {
        const int ir = band * 2 + b2;
        CP_WAIT_ALL();
        __syncthreads();
        if (b2 < 1) { fillB(ir + 1, 1); CP_COMMIT(); }

        const uint32_t ba0 = (uint32_t)(rc0 + ir * 224) >> 1;
        const uint32_t ba1 = (uint32_t)(rc1 + ir * 224) >> 1;
        const uint32_t bufoff = (uint32_t)(b2 * BSZ) * 4;
#pragma unroll
        for (int ks = 0; ks < 14; ks++) {
            uint32_t a0 = p0[ba0 + ks * 8 + t];
            uint32_t a2 = p0[ba0 + ks * 8 + t + 4];
            uint32_t a1 = p1[ba1 + ks * 8 + t];
            uint32_t a3 = p1[ba1 + ks * 8 + t + 4];
#pragma unroll
            for (int p = 0; p < 4; p++) {
                uint32_t b0, b1, b2r, b3;
                uint32_t addr = bsm + bufoff +
                    (uint32_t)((p * 16 + nrow_off) * BPITCH + ks * 8 + k_off) * 4;
                LDSM4(b0, b1, b2r, b3, addr);
                MMA16816(c[2 * p],     a0, a1, a2, a3, b0, b1);
                MMA16816(c[2 * p + 1], a0, a1, a2, a3, b2r, b3);
            }
        }
        __syncthreads();
    }

    float* dst = g_Cpart + ((size_t)band * 512 + kt * 128 + w * 16) * 64;
#pragma unroll
    for (int nt = 0; nt < 8; nt++) {
        *(float2*)&dst[(g)     * 64 + nt * 8 + 2 * t] = make_float2(c[nt][0], c[nt][1]);
        *(float2*)&dst[(g + 8) * 64 + nt * 8 + 2 * t] = make_float2(c[nt][2], c[nt][3]);
    }
}

// ======================================================================
// K3a: reduce stage 1: 110 bands -> 5 groups of 22. grid (37, 5).
// ======================================================================
__global__ void k_reduce1()
{
    int e = blockIdx.x * 256 + threadIdx.x;
    int gg = blockIdx.y;
    if (e < 8192) {
        const float4* P = (const float4*)g_Cpart;
        float4 s = make_float4(0.f, 0.f, 0.f, 0.f);
#pragma unroll 11
        for (int b = 0; b < 22; b++) {
            float4 v = P[(size_t)(gg * 22 + b) * 8192 + e];
            s.x += v.x; s.y += v.y; s.z += v.z; s.w += v.w;
        }
        ((float4*)g_Cred)[gg * 8192 + e] = s;
    } else if (e < 9216) {
        int i = e - 8192;
        const float4* P = (const float4*)g_ytypart;
        float4 s = make_float4(0.f, 0.f, 0.f, 0.f);
#pragma unroll 11
        for (int b = 0; b < 22; b++) {
            float4 v = P[(size_t)(gg * 22 + b) * 1024 + i];
            s.x += v.x; s.y += v.y; s.z += v.z; s.w += v.w;
        }
        ((float4*)g_ytyred)[gg * 1024 + i] = s;
    }
}

// ======================================================================
// K3b: reduce stage 2 (+ exp_new / gfp). grid 37.
// ======================================================================
__global__ void k_reduce2(const float* __restrict__ exp_avg,
                          float* __restrict__ dout)
{
    int e = blockIdx.x * 256 + threadIdx.x;
    if (e < 8192) {
        const float4* P = (const float4*)g_Cred;
        float4 s = make_float4(0.f, 0.f, 0.f, 0.f);
#pragma unroll
        for (int gg = 0; gg < NG; gg++) {
            float4 v = P[gg * 8192 + e];
            s.x += v.x; s.y += v.y; s.z += v.z; s.w += v.w;
        }
        ((float4*)g_Cfin)[e] = s;
    } else if (e < 9216) {
        int i = e - 8192;
        const float4* P = (const float4*)g_ytyred;
        float4 s = make_float4(0.f, 0.f, 0.f, 0.f);
#pragma unroll
        for (int gg = 0; gg < NG; gg++) {
            float4 v = P[gg * 1024 + i];
            s.x += v.x; s.y += v.y; s.z += v.z; s.w += v.w;
        }
        ((float4*)g_ytyF)[i] = s;
    }

    if (blockIdx.x == 36) {
        __shared__ float sh[OCH];
        int t = threadIdx.x;
        if (t < OCH) {
            float cs = 0.f;
#pragma unroll 10
            for (int b = 0; b < MB2; b++) cs += g_colpart[b * OCH + t];
            float en = 0.99f * exp_avg[t] + (1.0f - 0.99f) * (cs / (float)NB);
            sh[t] = en;
            dout[OUT_OFF_EXP + t] = en;
        }
        __syncthreads();
        if (t < OCH) {
            float s = 0.f;
            for (int i = 0; i < OCH; i++) s += sh[i];
            float A = sh[t] / (s * (1.0f / (float)OCH));
            g_gfp[t] = 0.01f * tanhf(-0.01f * (A - 1.0f)) + 1.0f;
        }
    }
}

// ======================================================================
// K4: weight update.
// ======================================================================
__global__ void k_wupd(const float* __restrict__ W, float* __restrict__ dout)
{
    int idx = blockIdx.x * 256 + threadIdx.x;
    if (idx >= OCH * KTOT) return;
    int oc = idx / KTOT;
    int k = idx - oc * KTOT;
    float dot = 0.f;
#pragma unroll 8
    for (int b = 0; b < OCH; b++)
        dot += g_ytyF[oc * OCH + b] * W[b * KTOT + k];
    const float LRN = (float)(0.005 / 48400.0);
    float d = LRN * (g_Cfin[k * 64 + oc] - dot);
    float wn = fmaxf(W[idx] + d, 0.f);
    dout[OUT_OFF_W + idx] = wn * g_gfp[oc];
}

// ======================================================================
extern "C" void kernel_launch(void* const* d_in, const int* in_sizes, int n_in,
                              void* d_out, int out_size)
{
    const float* x  = (const float*)d_in[0];
    const float* W  = (const float*)d_in[1];
    const float* ea = (const float*)d_in[2];
    float* dout = (float*)d_out;

    const int ytxf_smem = 2 * BSZ * 4;   // 59392 B
    cudaFuncSetAttribute(k_ytxf_mma,
                         cudaFuncAttributeMaxDynamicSharedMemorySize, ytxf_smem);

    k_cvt_x<<<(XSZ + 255) / 256, 256>>>(x);
    k_cvt_w<<<(OCH * KTOT + OCH * 440 + 255) / 256, 256>>>(W);
    dim3 g1(2, 220);
    k_conv_mma<<<g1, 224>>>(dout);
    k_yty_mma<<<MB2, 256>>>();
    dim3 g2(MB2, 4);
    k_ytxf_mma<<<g2, 256, ytxf_smem>>>();
    dim3 g3(37, NG);
    k_reduce1<<<g3, 256>>>();
    k_reduce2<<<37, 256>>>(ea, dout);
    k_wupd<<<100, 256>>>(W, dout);
}

// round 16
// speedup vs baseline: 1.1527x; 1.1527x over previous
#include <cuda_runtime.h>
#include <cuda_bf16.h>
#include <cstdint>

// ---------------- problem constants ----------------
#define INS   224
#define NH    220
#define NB    48400
#define ICH   16
#define OCH   64
#define KTOT  400
#define XSZ   (ICH*INS*INS)      // 802816

#define OUT_OFF_W   (OCH*NB)
#define OUT_OFF_EXP (OUT_OFF_W + OCH*KTOT)

#define MB2   110                // bands (2 image rows each)
#define NG    5                  // reduce stage-1 groups (22 bands each)
#define YROW  49280              // g_yh per-oc size: 220 rows x 224 (pad 4 = 0)

// ---------------- scratch ----------------
__device__ __nv_bfloat16 g_xh[XSZ];
__device__ __nv_bfloat16 g_xl[XSZ];
__device__ __nv_bfloat16 g_xhs[XSZ];         // bf16(x[e+1])
__device__ __nv_bfloat16 g_xls[XSZ];         // lo(x[e+1])
__device__ uint32_t g_xq_h[XSZ];             // pack(hi x[e], hi x[e+220])
__device__ uint32_t g_xq_l[XSZ];
__device__ uint32_t g_xr_h[XSZ];             // pack(hi x[e], hi x[e+49276])
__device__ uint32_t g_xr_l[XSZ];
__device__ __nv_bfloat16 g_Wh[OCH * KTOT];
__device__ __nv_bfloat16 g_Wl[OCH * KTOT];
__device__ __nv_bfloat16 g_yh[OCH * YROW];
__device__ float g_Cpart[MB2 * 512 * OCH];   // 14.4MB
__device__ float g_ytypart[MB2 * OCH * OCH];
__device__ float g_colpart[MB2 * OCH];
__device__ float g_Cred[NG * 512 * OCH];
__device__ float g_ytyred[NG * OCH * OCH];
__device__ float g_Cfin[512 * OCH];
__device__ float g_ytyF[OCH * OCH];
__device__ float g_gfp[OCH];

#define MMA16816(c, a0,a1,a2,a3, b0,b1) \
  asm volatile("mma.sync.aligned.m16n8k16.row.col.f32.bf16.bf16.f32 " \
    "{%0,%1,%2,%3},{%4,%5,%6,%7},{%8,%9},{%0,%1,%2,%3};" \
    : "+f"((c)[0]),"+f"((c)[1]),"+f"((c)[2]),"+f"((c)[3]) \
    : "r"(a0),"r"(a1),"r"(a2),"r"(a3),"r"(b0),"r"(b1))

#define LDSM4(r0,r1,r2,r3, saddr) \
  asm volatile("ldmatrix.sync.aligned.m8n8.x4.shared.b16 {%0,%1,%2,%3}, [%4];" \
    : "=r"(r0),"=r"(r1),"=r"(r2),"=r"(r3) : "r"(saddr))

#define CP_ASYNC4(saddr, gptr) \
  asm volatile("cp.async.ca.shared.global [%0], [%1], 4;" \
    :: "r"(saddr), "l"(gptr) : "memory")
#define CP_COMMIT()   asm volatile("cp.async.commit_group;" ::: "memory")
#define CP_WAIT_ALL() asm volatile("cp.async.wait_group 0;" ::: "memory")

__device__ __forceinline__ uint32_t smem_u32(const void* p) {
    return (uint32_t)__cvta_generic_to_shared(p);
}
__device__ __forceinline__ uint32_t pack_bf2(__nv_bfloat16 lo, __nv_bfloat16 hi) {
    unsigned short a = *(unsigned short*)&lo, b = *(unsigned short*)&hi;
    return (uint32_t)a | ((uint32_t)b << 16);
}

// ======================================================================
// K0a: x -> all bf16 pair arrays
// ======================================================================
__global__ void k_cvt_x(const float* __restrict__ x)
{
    int e = blockIdx.x * 256 + threadIdx.x;
    if (e >= XSZ) return;
    float v = x[e];
    __nv_bfloat16 h = __float2bfloat16(v);
    __nv_bfloat16 l = __float2bfloat16(v - __bfloat162float(h));
    g_xh[e] = h; g_xl[e] = l;

    float v1 = (e + 1 < XSZ) ? x[e + 1] : 0.f;
    __nv_bfloat16 h1 = __float2bfloat16(v1);
    g_xhs[e] = h1;
    g_xls[e] = __float2bfloat16(v1 - __bfloat162float(h1));

    float vq = (e + 220 < XSZ) ? x[e + 220] : 0.f;
    __nv_bfloat16 hq = __float2bfloat16(vq);
    __nv_bfloat16 lq = __float2bfloat16(vq - __bfloat162float(hq));
    g_xq_h[e] = pack_bf2(h, hq);
    g_xq_l[e] = pack_bf2(l, lq);

    float vr = (e + 49276 < XSZ) ? x[e + 49276] : 0.f;
    __nv_bfloat16 hr = __float2bfloat16(vr);
    __nv_bfloat16 lr = __float2bfloat16(vr - __bfloat162float(hr));
    g_xr_h[e] = pack_bf2(h, hr);
    g_xr_l[e] = pack_bf2(l, lr);
}

// ======================================================================
// K0b: W -> bf16 hi/lo ; zero g_yh row pads
// ======================================================================
__global__ void k_cvt_w(const float* __restrict__ W)
{
    int idx = blockIdx.x * 256 + threadIdx.x;
    if (idx < OCH * KTOT) {
        float v = W[idx];
        __nv_bfloat16 h = __float2bfloat16(v);
        g_Wh[idx] = h;
        g_Wl[idx] = __float2bfloat16(v - __bfloat162float(h));
    } else if (idx < OCH * KTOT + OCH * 220 * 2) {
        int p = idx - OCH * KTOT;
        int oc = p / 440, rem = p - oc * 440;
        int r = rem >> 1, half = rem & 1;
        uint32_t* yh32 = (uint32_t*)g_yh;
        yh32[((oc * YROW + r * 224 + 220) >> 1) + half] = 0u;
    }
}

// ======================================================================
// A pair-load for conv: element pair (kb, kb+1) at pixel column eb(+8).
// ======================================================================
__device__ __forceinline__ void loadpairs(int kb, int eb, int pxA,
    uint32_t& h0, uint32_t& h1, uint32_t& l0, uint32_t& l1)
{
    int q = kb / 5;
    int kj = kb - q * 5;
    int ic = q / 5;
    int e = q * 224 + ic * 49056 + eb + kj;
    if (kj == 4) {
        bool icx = (q - ic * 5) == 4;
        const uint32_t* ph = icx ? g_xr_h : g_xq_h;
        const uint32_t* pl = icx ? g_xr_l : g_xq_l;
        h0 = ph[e]; h1 = ph[e + 8];
        l0 = pl[e]; l1 = pl[e + 8];
    } else {
        int par = (pxA + kj) & 1;
        const uint32_t* ph = par ? (const uint32_t*)g_xhs : (const uint32_t*)g_xh;
        const uint32_t* pl = par ? (const uint32_t*)g_xls : (const uint32_t*)g_xl;
        int w0 = e >> 1;
        h0 = ph[w0]; h1 = ph[w0 + 4];
        l0 = pl[w0]; l1 = pl[w0 + 4];
    }
}

// ======================================================================
// K1: conv + inhibition (R14 verbatim). grid (2, 220), 224 thr.
// ======================================================================
#define WPITCH 20
#define WBUF   (64 * WPITCH)

__global__ void __launch_bounds__(224, 4)
k_conv_mma(float* __restrict__ dout)
{
    __shared__ uint32_t wsh[2 * WBUF];
    __shared__ uint32_t wsl[2 * WBUF];

    const int tid = threadIdx.x;
    const int w = tid >> 5, lane = tid & 31;
    const int g = lane >> 2, t = lane & 3;
    const int h = blockIdx.x;
    const int i = blockIdx.y;
    const int J0 = h * 108;
    const int pxA = (w << 4) + g;
    const int eb = i * 224 + J0 + pxA;

    const int nrow_off = ((lane >> 4) & 1) * 8 + (lane & 7);
    const int k_off = ((lane >> 3) & 1) * 4;
    const uint32_t wsh_s = smem_u32(wsh);
    const uint32_t wsl_s = smem_u32(wsl);
    const uint32_t* wh2g = (const uint32_t*)g_Wh;
    const uint32_t* wl2g = (const uint32_t*)g_Wl;

    float c[8][4];
#pragma unroll
    for (int nt = 0; nt < 8; nt++)
#pragma unroll
        for (int q = 0; q < 4; q++) c[nt][q] = 0.f;

    auto fillW = [&](int s, int buf) {
        const int nu = (s < 12) ? 16 : 8;
        const int base = s * 16;
        for (int idx = tid; idx < 64 * nu; idx += 224) {
            int row, u;
            if (nu == 16) { row = idx >> 4; u = idx & 15; }
            else          { row = idx >> 3; u = idx & 7;  }
            uint32_t so = (uint32_t)(buf * WBUF + row * WPITCH + u) * 4;
            CP_ASYNC4(wsh_s + so, wh2g + row * 200 + base + u);
            CP_ASYNC4(wsl_s + so, wl2g + row * 200 + base + u);
        }
    };

    fillW(0, 0);
    CP_COMMIT();

    for (int s = 0; s < 13; s++) {
        CP_WAIT_ALL();
        __syncthreads();
        if (s < 12) { fillW(s + 1, (s + 1) & 1); CP_COMMIT(); }

        const int k0s = s * 32;
        const int nks = (s < 12) ? 2 : 1;
        const uint32_t bufoff = (uint32_t)((s & 1) * WBUF) * 4;

        for (int ksl = 0; ksl < nks; ksl++) {
            const int kb0 = k0s + ksl * 16 + 2 * t;
            uint32_t ah0, ah1, al0, al1, ah2, ah3, al2, al3;
            loadpairs(kb0,     eb, pxA, ah0, ah1, al0, al1);
            loadpairs(kb0 + 8, eb, pxA, ah2, ah3, al2, al3);

            const uint32_t wbase = bufoff +
                ((uint32_t)(nrow_off * WPITCH + ksl * 8 + k_off)) * 4;
#pragma unroll
            for (int p = 0; p < 4; p++) {
                uint32_t bh0, bh1, bh2, bh3, bl0, bl1, bl2, bl3;
                const uint32_t off = wbase + (uint32_t)(p * 16 * WPITCH) * 4;
                LDSM4(bh0, bh1, bh2, bh3, wsh_s + off);
                LDSM4(bl0, bl1, bl2, bl3, wsl_s + off);
                MMA16816(c[2 * p],     ah0, ah1, ah2, ah3, bh0, bh1);
                MMA16816(c[2 * p],     al0, al1, al2, al3, bh0, bh1);
                MMA16816(c[2 * p],     ah0, ah1, ah2, ah3, bl0, bl1);
                MMA16816(c[2 * p + 1], ah0, ah1, ah2, ah3, bh2, bh3);
                MMA16816(c[2 * p + 1], al0, al1, al2, al3, bh2, bh3);
                MMA16816(c[2 * p + 1], ah0, ah1, ah2, ah3, bl2, bl3);
            }
        }
        __syncthreads();
    }

    // ---- inhibition + writeback ----
    float m0 = 0.f, m1 = 0.f;
#pragma unroll
    for (int nt = 0; nt < 8; nt++) {
        m0 = fmaxf(m0, fmaxf(c[nt][0], c[nt][1]));
        m1 = fmaxf(m1, fmaxf(c[nt][2], c[nt][3]));
    }
    m0 = fmaxf(m0, __shfl_xor_sync(0xFFFFFFFFu, m0, 1));
    m0 = fmaxf(m0, __shfl_xor_sync(0xFFFFFFFFu, m0, 2));
    m1 = fmaxf(m1, __shfl_xor_sync(0xFFFFFFFFu, m1, 1));
    m1 = fmaxf(m1, __shfl_xor_sync(0xFFFFFFFFu, m1, 2));
    const float inv0 = 1.f / (m0 + 1e-9f);
    const float inv1 = 1.f / (m1 + 1e-9f);

    const int pxg = i * NH + J0 + pxA;
    const int pyg = i * 224 + J0 + pxA;
#pragma unroll
    for (int nt = 0; nt < 8; nt++) {
        const int oc = nt * 8 + 2 * t;
        float v;
        v = fmaxf(c[nt][0], 0.f) * inv0; v = (v * v) * (v * v) * v;
        dout[(size_t)oc * NB + pxg] = v;
        g_yh[(size_t)oc * YROW + pyg] = __float2bfloat16(v);
        v = fmaxf(c[nt][1], 0.f) * inv0; v = (v * v) * (v * v) * v;
        dout[(size_t)(oc + 1) * NB + pxg] = v;
        g_yh[(size_t)(oc + 1) * YROW + pyg] = __float2bfloat16(v);
        v = fmaxf(c[nt][2], 0.f) * inv1; v = (v * v) * (v * v) * v;
        dout[(size_t)oc * NB + pxg + 8] = v;
        g_yh[(size_t)oc * YROW + pyg + 8] = __float2bfloat16(v);
        v = fmaxf(c[nt][3], 0.f) * inv1; v = (v * v) * (v * v) * v;
        dout[(size_t)(oc + 1) * NB + pxg + 8] = v;
        g_yh[(size_t)(oc + 1) * YROW + pyg + 8] = __float2bfloat16(v);
    }
}

// ======================================================================
// K2: y^T @ xf + fused yty slice + colsums slice.
// grid (110, 4) = 440 blocks (one wave at 3/SM), 256 thr,
// 59.4KB dyn smem, cp.async double-buffered B.
// kt block also computes yty rows [kt*16, kt*16+16) and colsums for
// oc in [kt*16, kt*16+16) directly from its smem B tile.
// ======================================================================
#define BPITCH 116
#define BSZ    (64 * BPITCH)       // 7424 u32 per buffer

extern __shared__ uint32_t s_B[];  // 2 * BSZ

__global__ void __launch_bounds__(256, 3)
k_ytxf_mma()
{
    const int tid  = threadIdx.x;
    const int band = blockIdx.x;     // rows 2*band, 2*band+1
    const int kt   = blockIdx.y;
    const int w    = tid >> 5;
    const int lane = tid & 31;
    const int g    = lane >> 2;
    const int t    = lane & 3;

    const uint32_t* yh32 = (const uint32_t*)g_yh;
    const uint32_t* xh32  = (const uint32_t*)g_xh;
    const uint32_t* xhs32 = (const uint32_t*)g_xhs;

    int rA = kt * 128 + w * 16 + g;
    int rB = rA + 8;
    int rc0 = 0, rc1 = 0;
    const uint32_t *p0 = xh32, *p1 = xh32;
    if (rA < KTOT) {
        int ic = rA / 25, rem = rA - ic * 25;
        int ki = rem / 5, kj = rem - ki * 5;
        rc0 = ic * 50176 + ki * 224 + kj;
        if (kj & 1) p0 = xhs32;
    }
    if (rB < KTOT) {
        int ic = rB / 25, rem = rB - ic * 25;
        int ki = rem / 5, kj = rem - ki * 5;
        rc1 = ic * 50176 + ki * 224 + kj;
        if (kj & 1) p1 = xhs32;
    }

    const uint32_t bsm = smem_u32(s_B);
    const int nrow_off = ((lane >> 4) & 1) * 8 + (lane & 7);
    const int k_off = ((lane >> 3) & 1) * 4;

    // zero the pad words of both buffers
    {
        int buf = tid >> 7, rem = tid & 127;
        int row = rem >> 1, p = rem & 1;
        s_B[buf * BSZ + row * BPITCH + 110 + p] = 0u;
    }

    auto fillB = [&](int ir, int buf) {
        for (int idx = tid; idx < 64 * 112; idx += 256) {
            int row = idx / 112, pc = idx - row * 112;
            if (pc < 110) {
                uint32_t so = (uint32_t)(buf * BSZ + row * BPITCH + pc) * 4;
                CP_ASYNC4(bsm + so, yh32 + ((row * YROW + ir * 224) >> 1) + pc);
            }
        }
    };

    float c[8][4];
#pragma unroll
    for (int n = 0; n < 8; n++)
#pragma unroll
        for (int q = 0; q < 4; q++) c[n][q] = 0.f;
    float cy[4] = {0.f, 0.f, 0.f, 0.f};     // yty slice tile (M16 x N8)
    float csum = 0.f;                        // colsum partial

    // colsum lane mapping: 16-thread groups within each warp
    const int ocl = tid >> 4;                // 0..15 -> oc = kt*16 + ocl
    const int cq  = tid & 15;                // 7 u32 each

    fillB(band * 2, 0);
    CP_COMMIT();

#pragma unroll
    for (int b2 = 0; b2 < 2; b2++) {
        const int ir = band * 2 + b2;
        CP_WAIT_ALL();
        __syncthreads();
        if (b2 < 1) { fillB(ir + 1, 1); CP_COMMIT(); }

        const uint32_t ba0 = (uint32_t)(rc0 + ir * 224) >> 1;
        const uint32_t ba1 = (uint32_t)(rc1 + ir * 224) >> 1;
        const uint32_t bufoff = (uint32_t)(b2 * BSZ) * 4;

        // ---- ytxf main ----
#pragma unroll
        for (int ks = 0; ks < 14; ks++) {
            uint32_t a0 = p0[ba0 + ks * 8 + t];
            uint32_t a2 = p0[ba0 + ks * 8 + t + 4];
            uint32_t a1 = p1[ba1 + ks * 8 + t];
            uint32_t a3 = p1[ba1 + ks * 8 + t + 4];
#pragma unroll
            for (int p = 0; p < 4; p++) {
                uint32_t b0, b1, b2r, b3;
                uint32_t addr = bsm + bufoff +
                    (uint32_t)((p * 16 + nrow_off) * BPITCH + ks * 8 + k_off) * 4;
                LDSM4(b0, b1, b2r, b3, addr);
                MMA16816(c[2 * p],     a0, a1, a2, a3, b0, b1);
                MMA16816(c[2 * p + 1], a0, a1, a2, a3, b2r, b3);
            }
        }

        // ---- yty slice: A rows kt*16.. from smem, warp w = n-tile w ----
        {
            const uint32_t aaddr0 = bsm + bufoff +
                (uint32_t)((kt * 16 + nrow_off) * BPITCH + k_off) * 4;
            const uint32_t* Bp = s_B + b2 * BSZ + (w * 8 + g) * BPITCH + t;
#pragma unroll
            for (int ks = 0; ks < 14; ks++) {
                uint32_t a0, a1, a2, a3;
                LDSM4(a0, a2, a1, a3, aaddr0 + (uint32_t)(ks * 8) * 4);
                uint32_t b0 = Bp[ks * 8];
                uint32_t b1 = Bp[ks * 8 + 4];
                MMA16816(cy, a0, a1, a2, a3, b0, b1);
            }
        }

        // ---- colsum slice: oc rows kt*16..+16 of smem tile ----
        {
            const uint32_t* Bp = s_B + b2 * BSZ + (kt * 16 + ocl) * BPITCH + cq * 7;
            float s = 0.f;
#pragma unroll
            for (int k = 0; k < 7; k++) {
                uint32_t v = Bp[k];
                __nv_bfloat162 hh = *(__nv_bfloat162*)&v;
                float2 f = __bfloat1622float2(hh);
                s += f.x + f.y;
            }
            csum += s;
        }

        __syncthreads();
    }

    // ---- epilogues ----
    float* dst = g_Cpart + ((size_t)band * 512 + kt * 128 + w * 16) * 64;
#pragma unroll
    for (int nt = 0; nt < 8; nt++) {
        *(float2*)&dst[(g)     * 64 + nt * 8 + 2 * t] = make_float2(c[nt][0], c[nt][1]);
        *(float2*)&dst[(g + 8) * 64 + nt * 8 + 2 * t] = make_float2(c[nt][2], c[nt][3]);
    }

    float* ydst = g_ytypart + (size_t)band * 4096;
    {
        const int col = w * 8 + 2 * t;
        *(float2*)&ydst[(kt * 16 + g) * 64 + col]     = make_float2(cy[0], cy[1]);
        *(float2*)&ydst[(kt * 16 + g + 8) * 64 + col] = make_float2(cy[2], cy[3]);
    }

    // reduce colsums within 16-lane groups
    csum += __shfl_xor_sync(0xFFFFFFFFu, csum, 1);
    csum += __shfl_xor_sync(0xFFFFFFFFu, csum, 2);
    csum += __shfl_xor_sync(0xFFFFFFFFu, csum, 4);
    csum += __shfl_xor_sync(0xFFFFFFFFu, csum, 8);
    if (cq == 0) g_colpart[band * OCH + kt * 16 + ocl] = csum;
}

// ======================================================================
// K3a: reduce stage 1: 110 bands -> 5 groups of 22. grid (37, 5).
// ======================================================================
__global__ void k_reduce1()
{
    int e = blockIdx.x * 256 + threadIdx.x;
    int gg = blockIdx.y;
    if (e < 8192) {
        const float4* P = (const float4*)g_Cpart;
        float4 s = make_float4(0.f, 0.f, 0.f, 0.f);
#pragma unroll 11
        for (int b = 0; b < 22; b++) {
            float4 v = P[(size_t)(gg * 22 + b) * 8192 + e];
            s.x += v.x; s.y += v.y; s.z += v.z; s.w += v.w;
        }
        ((float4*)g_Cred)[gg * 8192 + e] = s;
    } else if (e < 9216) {
        int i = e - 8192;
        const float4* P = (const float4*)g_ytypart;
        float4 s = make_float4(0.f, 0.f, 0.f, 0.f);
#pragma unroll 11
        for (int b = 0; b < 22; b++) {
            float4 v = P[(size_t)(gg * 22 + b) * 1024 + i];
            s.x += v.x; s.y += v.y; s.z += v.z; s.w += v.w;
        }
        ((float4*)g_ytyred)[gg * 1024 + i] = s;
    }
}

// ======================================================================
// K3b: reduce stage 2 (+ exp_new / gfp). grid 37.
// ======================================================================
__global__ void k_reduce2(const float* __restrict__ exp_avg,
                          float* __restrict__ dout)
{
    int e = blockIdx.x * 256 + threadIdx.x;
    if (e < 8192) {
        const float4* P = (const float4*)g_Cred;
        float4 s = make_float4(0.f, 0.f, 0.f, 0.f);
#pragma unroll
        for (int gg = 0; gg < NG; gg++) {
            float4 v = P[gg * 8192 + e];
            s.x += v.x; s.y += v.y; s.z += v.z; s.w += v.w;
        }
        ((float4*)g_Cfin)[e] = s;
    } else if (e < 9216) {
        int i = e - 8192;
        const float4* P = (const float4*)g_ytyred;
        float4 s = make_float4(0.f, 0.f, 0.f, 0.f);
#pragma unroll
        for (int gg = 0; gg < NG; gg++) {
            float4 v = P[gg * 1024 + i];
            s.x += v.x; s.y += v.y; s.z += v.z; s.w += v.w;
        }
        ((float4*)g_ytyF)[i] = s;
    }

    if (blockIdx.x == 36) {
        __shared__ float sh[OCH];
        int t = threadIdx.x;
        if (t < OCH) {
            float cs = 0.f;
#pragma unroll 10
            for (int b = 0; b < MB2; b++) cs += g_colpart[b * OCH + t];
            float en = 0.99f * exp_avg[t] + (1.0f - 0.99f) * (cs / (float)NB);
            sh[t] = en;
            dout[OUT_OFF_EXP + t] = en;
        }
        __syncthreads();
        if (t < OCH) {
            float s = 0.f;
            for (int i = 0; i < OCH; i++) s += sh[i];
            float A = sh[t] / (s * (1.0f / (float)OCH));
            g_gfp[t] = 0.01f * tanhf(-0.01f * (A - 1.0f)) + 1.0f;
        }
    }
}

// ======================================================================
// K4: weight update.
// ======================================================================
__global__ void k_wupd(const float* __restrict__ W, float* __restrict__ dout)
{
    int idx = blockIdx.x * 256 + threadIdx.x;
    if (idx >= OCH * KTOT) return;
    int oc = idx / KTOT;
    int k = idx - oc * KTOT;
    float dot = 0.f;
#pragma unroll 8
    for (int b = 0; b < OCH; b++)
        dot += g_ytyF[oc * OCH + b] * W[b * KTOT + k];
    const float LRN = (float)(0.005 / 48400.0);
    float d = LRN * (g_Cfin[k * 64 + oc] - dot);
    float wn = fmaxf(W[idx] + d, 0.f);
    dout[OUT_OFF_W + idx] = wn * g_gfp[oc];
}

// ======================================================================
extern "C" void kernel_launch(void* const* d_in, const int* in_sizes, int n_in,
                              void* d_out, int out_size)
{
    const float* x  = (const float*)d_in[0];
    const float* W  = (const float*)d_in[1];
    const float* ea = (const float*)d_in[2];
    float* dout = (float*)d_out;

    const int ytxf_smem = 2 * BSZ * 4;   // 59392 B
    cudaFuncSetAttribute(k_ytxf_mma,
                         cudaFuncAttributeMaxDynamicSharedMemorySize, ytxf_smem);

    k_cvt_x<<<(XSZ + 255) / 256, 256>>>(x);
    k_cvt_w<<<(OCH * KTOT + OCH * 440 + 255) / 256, 256>>>(W);
    dim3 g1(2, 220);
    k_conv_mma<<<g1, 224>>>(dout);
    dim3 g2(MB2, 4);
    k_ytxf_mma<<<g2, 256, ytxf_smem>>>();
    dim3 g3(37, NG);
    k_reduce1<<<g3, 256>>>();
    k_reduce2<<<37, 256>>>(ea, dout);
    k_wupd<<<100, 256>>>(W, dout);
}

// round 17
// speedup vs baseline: 1.1679x; 1.0132x over previous
#include <cuda_runtime.h>
#include <cuda_bf16.h>
#include <cstdint>

// ---------------- problem constants ----------------
#define INS   224
#define NH    220
#define NB    48400
#define ICH   16
#define OCH   64
#define KTOT  400
#define XSZ   (ICH*INS*INS)      // 802816

#define OUT_OFF_W   (OCH*NB)
#define OUT_OFF_EXP (OUT_OFF_W + OCH*KTOT)

#define MB2   110                // bands (2 image rows each)
#define NG    5                  // reduce stage-1 groups (22 bands each)
#define YROW  49280              // g_yh per-oc size: 220 rows x 224 (pad 4 = 0)

// ---------------- scratch ----------------
__device__ __nv_bfloat16 g_xh[XSZ];
__device__ __nv_bfloat16 g_xl[XSZ];
__device__ __nv_bfloat16 g_xhs[XSZ];         // bf16(x[e+1])
__device__ __nv_bfloat16 g_xls[XSZ];         // lo(x[e+1])
__device__ uint32_t g_xq_h[XSZ];             // pack(hi x[e], hi x[e+220])
__device__ uint32_t g_xq_l[XSZ];
__device__ uint32_t g_xr_h[XSZ];             // pack(hi x[e], hi x[e+49276])
__device__ uint32_t g_xr_l[XSZ];
__device__ __nv_bfloat16 g_Wh[OCH * KTOT];
__device__ __nv_bfloat16 g_Wl[OCH * KTOT];
__device__ __nv_bfloat16 g_yh[OCH * YROW];
__device__ float g_Cpart[MB2 * 512 * OCH];   // 14.4MB
__device__ float g_ytypart[MB2 * OCH * OCH];
__device__ float g_colpart[MB2 * OCH];
__device__ float g_Cred[NG * 512 * OCH];
__device__ float g_ytyred[NG * OCH * OCH];
__device__ float g_Cfin[512 * OCH];
__device__ float g_ytyF[OCH * OCH];
__device__ float g_gfp[OCH];

#define MMA16816(c, a0,a1,a2,a3, b0,b1) \
  asm volatile("mma.sync.aligned.m16n8k16.row.col.f32.bf16.bf16.f32 " \
    "{%0,%1,%2,%3},{%4,%5,%6,%7},{%8,%9},{%0,%1,%2,%3};" \
    : "+f"((c)[0]),"+f"((c)[1]),"+f"((c)[2]),"+f"((c)[3]) \
    : "r"(a0),"r"(a1),"r"(a2),"r"(a3),"r"(b0),"r"(b1))

#define LDSM4(r0,r1,r2,r3, saddr) \
  asm volatile("ldmatrix.sync.aligned.m8n8.x4.shared.b16 {%0,%1,%2,%3}, [%4];" \
    : "=r"(r0),"=r"(r1),"=r"(r2),"=r"(r3) : "r"(saddr))

#define CP_ASYNC4(saddr, gptr) \
  asm volatile("cp.async.ca.shared.global [%0], [%1], 4;" \
    :: "r"(saddr), "l"(gptr) : "memory")
#define CP_COMMIT()   asm volatile("cp.async.commit_group;" ::: "memory")
#define CP_WAIT_ALL() asm volatile("cp.async.wait_group 0;" ::: "memory")

__device__ __forceinline__ uint32_t smem_u32(const void* p) {
    return (uint32_t)__cvta_generic_to_shared(p);
}
__device__ __forceinline__ uint32_t pack_bf2(__nv_bfloat16 lo, __nv_bfloat16 hi) {
    unsigned short a = *(unsigned short*)&lo, b = *(unsigned short*)&hi;
    return (uint32_t)a | ((uint32_t)b << 16);
}

// ======================================================================
// K0a: x -> all bf16 pair arrays
// ======================================================================
__global__ void k_cvt_x(const float* __restrict__ x)
{
    int e = blockIdx.x * 256 + threadIdx.x;
    if (e >= XSZ) return;
    float v = x[e];
    __nv_bfloat16 h = __float2bfloat16(v);
    __nv_bfloat16 l = __float2bfloat16(v - __bfloat162float(h));
    g_xh[e] = h; g_xl[e] = l;

    float v1 = (e + 1 < XSZ) ? x[e + 1] : 0.f;
    __nv_bfloat16 h1 = __float2bfloat16(v1);
    g_xhs[e] = h1;
    g_xls[e] = __float2bfloat16(v1 - __bfloat162float(h1));

    float vq = (e + 220 < XSZ) ? x[e + 220] : 0.f;
    __nv_bfloat16 hq = __float2bfloat16(vq);
    __nv_bfloat16 lq = __float2bfloat16(vq - __bfloat162float(hq));
    g_xq_h[e] = pack_bf2(h, hq);
    g_xq_l[e] = pack_bf2(l, lq);

    float vr = (e + 49276 < XSZ) ? x[e + 49276] : 0.f;
    __nv_bfloat16 hr = __float2bfloat16(vr);
    __nv_bfloat16 lr = __float2bfloat16(vr - __bfloat162float(hr));
    g_xr_h[e] = pack_bf2(h, hr);
    g_xr_l[e] = pack_bf2(l, lr);
}

// ======================================================================
// K0b: W -> bf16 hi/lo ; zero g_yh row pads
// ======================================================================
__global__ void k_cvt_w(const float* __restrict__ W)
{
    int idx = blockIdx.x * 256 + threadIdx.x;
    if (idx < OCH * KTOT) {
        float v = W[idx];
        __nv_bfloat16 h = __float2bfloat16(v);
        g_Wh[idx] = h;
        g_Wl[idx] = __float2bfloat16(v - __bfloat162float(h));
    } else if (idx < OCH * KTOT + OCH * 220 * 2) {
        int p = idx - OCH * KTOT;
        int oc = p / 440, rem = p - oc * 440;
        int r = rem >> 1, half = rem & 1;
        uint32_t* yh32 = (uint32_t*)g_yh;
        yh32[((oc * YROW + r * 224 + 220) >> 1) + half] = 0u;
    }
}

// ======================================================================
// A pair-load for conv: element pair (kb, kb+1) at pixel column eb(+8).
// ======================================================================
__device__ __forceinline__ void loadpairs(int kb, int eb, int pxA,
    uint32_t& h0, uint32_t& h1, uint32_t& l0, uint32_t& l1)
{
    int q = kb / 5;
    int kj = kb - q * 5;
    int ic = q / 5;
    int e = q * 224 + ic * 49056 + eb + kj;
    if (kj == 4) {
        bool icx = (q - ic * 5) == 4;
        const uint32_t* ph = icx ? g_xr_h : g_xq_h;
        const uint32_t* pl = icx ? g_xr_l : g_xq_l;
        h0 = ph[e]; h1 = ph[e + 8];
        l0 = pl[e]; l1 = pl[e + 8];
    } else {
        int par = (pxA + kj) & 1;
        const uint32_t* ph = par ? (const uint32_t*)g_xhs : (const uint32_t*)g_xh;
        const uint32_t* pl = par ? (const uint32_t*)g_xls : (const uint32_t*)g_xl;
        int w0 = e >> 1;
        h0 = ph[w0]; h1 = ph[w0 + 4];
        l0 = pl[w0]; l1 = pl[w0 + 4];
    }
}

// ======================================================================
// K1: conv + inhibition, split-bf16 MMA, W cp.async double-buffered,
// A-loads software-pipelined one ksl-step ahead.
// grid (2, 220) = 440 blocks (single wave at 3/SM), 224 thr.
// ======================================================================
#define WPITCH 20
#define WBUF   (64 * WPITCH)

__global__ void __launch_bounds__(224, 3)
k_conv_mma(float* __restrict__ dout)
{
    __shared__ uint32_t wsh[2 * WBUF];
    __shared__ uint32_t wsl[2 * WBUF];

    const int tid = threadIdx.x;
    const int w = tid >> 5, lane = tid & 31;
    const int g = lane >> 2, t = lane & 3;
    const int h = blockIdx.x;
    const int i = blockIdx.y;
    const int J0 = h * 108;
    const int pxA = (w << 4) + g;
    const int eb = i * 224 + J0 + pxA;

    const int nrow_off = ((lane >> 4) & 1) * 8 + (lane & 7);
    const int k_off = ((lane >> 3) & 1) * 4;
    const uint32_t wsh_s = smem_u32(wsh);
    const uint32_t wsl_s = smem_u32(wsl);
    const uint32_t* wh2g = (const uint32_t*)g_Wh;
    const uint32_t* wl2g = (const uint32_t*)g_Wl;

    float c[8][4];
#pragma unroll
    for (int nt = 0; nt < 8; nt++)
#pragma unroll
        for (int q = 0; q < 4; q++) c[nt][q] = 0.f;

    auto fillW = [&](int s, int buf) {
        const int nu = (s < 12) ? 16 : 8;
        const int base = s * 16;
        for (int idx = tid; idx < 64 * nu; idx += 224) {
            int row, u;
            if (nu == 16) { row = idx >> 4; u = idx & 15; }
            else          { row = idx >> 3; u = idx & 7;  }
            uint32_t so = (uint32_t)(buf * WBUF + row * WPITCH + u) * 4;
            CP_ASYNC4(wsh_s + so, wh2g + row * 200 + base + u);
            CP_ASYNC4(wsl_s + so, wl2g + row * 200 + base + u);
        }
    };

    // compute one ksl-step with given A regs
    auto compute = [&](const uint32_t* A, uint32_t bufoff, int ksl) {
        const uint32_t wbase = bufoff +
            ((uint32_t)(nrow_off * WPITCH + ksl * 8 + k_off)) * 4;
#pragma unroll
        for (int p = 0; p < 4; p++) {
            uint32_t bh0, bh1, bh2, bh3, bl0, bl1, bl2, bl3;
            const uint32_t off = wbase + (uint32_t)(p * 16 * WPITCH) * 4;
            LDSM4(bh0, bh1, bh2, bh3, wsh_s + off);
            LDSM4(bl0, bl1, bl2, bl3, wsl_s + off);
            MMA16816(c[2 * p],     A[0], A[1], A[2], A[3], bh0, bh1);
            MMA16816(c[2 * p],     A[4], A[5], A[6], A[7], bh0, bh1);
            MMA16816(c[2 * p],     A[0], A[1], A[2], A[3], bl0, bl1);
            MMA16816(c[2 * p + 1], A[0], A[1], A[2], A[3], bh2, bh3);
            MMA16816(c[2 * p + 1], A[4], A[5], A[6], A[7], bh2, bh3);
            MMA16816(c[2 * p + 1], A[0], A[1], A[2], A[3], bl2, bl3);
        }
    };

    fillW(0, 0);
    CP_COMMIT();

    // A register double-buffer: A0 = current even ksl, A1 = odd ksl.
    uint32_t A0[8], A1[8];
    {   // prologue: A(s=0, ksl=0)
        const int kb = 2 * t;
        loadpairs(kb,     eb, pxA, A0[0], A0[1], A0[4], A0[5]);
        loadpairs(kb + 8, eb, pxA, A0[2], A0[3], A0[6], A0[7]);
    }

    for (int s = 0; s < 13; s++) {
        CP_WAIT_ALL();
        __syncthreads();
        if (s < 12) { fillW(s + 1, (s + 1) & 1); CP_COMMIT(); }

        const int k0s = s * 32;
        const uint32_t bufoff = (uint32_t)((s & 1) * WBUF) * 4;

        if (s < 12) {
            // prefetch A(s, ksl=1)
            const int kb = k0s + 16 + 2 * t;
            loadpairs(kb,     eb, pxA, A1[0], A1[1], A1[4], A1[5]);
            loadpairs(kb + 8, eb, pxA, A1[2], A1[3], A1[6], A1[7]);

            compute(A0, bufoff, 0);

            // prefetch A(s+1, ksl=0)
            const int kbn = (s + 1) * 32 + 2 * t;
            loadpairs(kbn,     eb, pxA, A0[0], A0[1], A0[4], A0[5]);
            loadpairs(kbn + 8, eb, pxA, A0[2], A0[3], A0[6], A0[7]);

            compute(A1, bufoff, 1);
        } else {
            compute(A0, bufoff, 0);   // last chunk: single ksl
        }
        __syncthreads();
    }

    // ---- inhibition + writeback ----
    float m0 = 0.f, m1 = 0.f;
#pragma unroll
    for (int nt = 0; nt < 8; nt++) {
        m0 = fmaxf(m0, fmaxf(c[nt][0], c[nt][1]));
        m1 = fmaxf(m1, fmaxf(c[nt][2], c[nt][3]));
    }
    m0 = fmaxf(m0, __shfl_xor_sync(0xFFFFFFFFu, m0, 1));
    m0 = fmaxf(m0, __shfl_xor_sync(0xFFFFFFFFu, m0, 2));
    m1 = fmaxf(m1, __shfl_xor_sync(0xFFFFFFFFu, m1, 1));
    m1 = fmaxf(m1, __shfl_xor_sync(0xFFFFFFFFu, m1, 2));
    const float inv0 = 1.f / (m0 + 1e-9f);
    const float inv1 = 1.f / (m1 + 1e-9f);

    const int pxg = i * NH + J0 + pxA;
    const int pyg = i * 224 + J0 + pxA;
#pragma unroll
    for (int nt = 0; nt < 8; nt++) {
        const int oc = nt * 8 + 2 * t;
        float v;
        v = fmaxf(c[nt][0], 0.f) * inv0; v = (v * v) * (v * v) * v;
        dout[(size_t)oc * NB + pxg] = v;
        g_yh[(size_t)oc * YROW + pyg] = __float2bfloat16(v);
        v = fmaxf(c[nt][1], 0.f) * inv0; v = (v * v) * (v * v) * v;
        dout[(size_t)(oc + 1) * NB + pxg] = v;
        g_yh[(size_t)(oc + 1) * YROW + pyg] = __float2bfloat16(v);
        v = fmaxf(c[nt][2], 0.f) * inv1; v = (v * v) * (v * v) * v;
        dout[(size_t)oc * NB + pxg + 8] = v;
        g_yh[(size_t)oc * YROW + pyg + 8] = __float2bfloat16(v);
        v = fmaxf(c[nt][3], 0.f) * inv1; v = (v * v) * (v * v) * v;
        dout[(size_t)(oc + 1) * NB + pxg + 8] = v;
        g_yh[(size_t)(oc + 1) * YROW + pyg + 8] = __float2bfloat16(v);
    }
}

// ======================================================================
// K2: y^T @ xf + fused yty slice + colsums slice. (R16 verbatim)
// grid (110, 4), 256 thr, 59.4KB dyn smem.
// ======================================================================
#define BPITCH 116
#define BSZ    (64 * BPITCH)       // 7424 u32 per buffer

extern __shared__ uint32_t s_B[];  // 2 * BSZ

__global__ void __launch_bounds__(256, 3)
k_ytxf_mma()
{
    const int tid  = threadIdx.x;
    const int band = blockIdx.x;     // rows 2*band, 2*band+1
    const int kt   = blockIdx.y;
    const int w    = tid >> 5;
    const int lane = tid & 31;
    const int g    = lane >> 2;
    const int t    = lane & 3;

    const uint32_t* yh32 = (const uint32_t*)g_yh;
    const uint32_t* xh32  = (const uint32_t*)g_xh;
    const uint32_t* xhs32 = (const uint32_t*)g_xhs;

    int rA = kt * 128 + w * 16 + g;
    int rB = rA + 8;
    int rc0 = 0, rc1 = 0;
    const uint32_t *p0 = xh32, *p1 = xh32;
    if (rA < KTOT) {
        int ic = rA / 25, rem = rA - ic * 25;
        int ki = rem / 5, kj = rem - ki * 5;
        rc0 = ic * 50176 + ki * 224 + kj;
        if (kj & 1) p0 = xhs32;
    }
    if (rB < KTOT) {
        int ic = rB / 25, rem = rB - ic * 25;
        int ki = rem / 5, kj = rem - ki * 5;
        rc1 = ic * 50176 + ki * 224 + kj;
        if (kj & 1) p1 = xhs32;
    }

    const uint32_t bsm = smem_u32(s_B);
    const int nrow_off = ((lane >> 4) & 1) * 8 + (lane & 7);
    const int k_off = ((lane >> 3) & 1) * 4;

    // zero the pad words of both buffers
    {
        int buf = tid >> 7, rem = tid & 127;
        int row = rem >> 1, p = rem & 1;
        s_B[buf * BSZ + row * BPITCH + 110 + p] = 0u;
    }

    auto fillB = [&](int ir, int buf) {
        for (int idx = tid; idx < 64 * 112; idx += 256) {
            int row = idx / 112, pc = idx - row * 112;
            if (pc < 110) {
                uint32_t so = (uint32_t)(buf * BSZ + row * BPITCH + pc) * 4;
                CP_ASYNC4(bsm + so, yh32 + ((row * YROW + ir * 224) >> 1) + pc);
            }
        }
    };

    float c[8][4];
#pragma unroll
    for (int n = 0; n < 8; n++)
#pragma unroll
        for (int q = 0; q < 4; q++) c[n][q] = 0.f;
    float cy[4] = {0.f, 0.f, 0.f, 0.f};
    float csum = 0.f;

    const int ocl = tid >> 4;
    const int cq  = tid & 15;

    fillB(band * 2, 0);
    CP_COMMIT();

#pragma unroll
    for (int b2 = 0; b2 < 2; b2++) {
        const int ir = band * 2 + b2;
        CP_WAIT_ALL();
        __syncthreads();
        if (b2 < 1) { fillB(ir + 1, 1); CP_COMMIT(); }

        const uint32_t ba0 = (uint32_t)(rc0 + ir * 224) >> 1;
        const uint32_t ba1 = (uint32_t)(rc1 + ir * 224) >> 1;
        const uint32_t bufoff = (uint32_t)(b2 * BSZ) * 4;

#pragma unroll
        for (int ks = 0; ks < 14; ks++) {
            uint32_t a0 = p0[ba0 + ks * 8 + t];
            uint32_t a2 = p0[ba0 + ks * 8 + t + 4];
            uint32_t a1 = p1[ba1 + ks * 8 + t];
            uint32_t a3 = p1[ba1 + ks * 8 + t + 4];
#pragma unroll
            for (int p = 0; p < 4; p++) {
                uint32_t b0, b1, b2r, b3;
                uint32_t addr = bsm + bufoff +
                    (uint32_t)((p * 16 + nrow_off) * BPITCH + ks * 8 + k_off) * 4;
                LDSM4(b0, b1, b2r, b3, addr);
                MMA16816(c[2 * p],     a0, a1, a2, a3, b0, b1);
                MMA16816(c[2 * p + 1], a0, a1, a2, a3, b2r, b3);
            }
        }

        {
            const uint32_t aaddr0 = bsm + bufoff +
                (uint32_t)((kt * 16 + nrow_off) * BPITCH + k_off) * 4;
            const uint32_t* Bp = s_B + b2 * BSZ + (w * 8 + g) * BPITCH + t;
#pragma unroll
            for (int ks = 0; ks < 14; ks++) {
                uint32_t a0, a1, a2, a3;
                LDSM4(a0, a2, a1, a3, aaddr0 + (uint32_t)(ks * 8) * 4);
                uint32_t b0 = Bp[ks * 8];
                uint32_t b1 = Bp[ks * 8 + 4];
                MMA16816(cy, a0, a1, a2, a3, b0, b1);
            }
        }

        {
            const uint32_t* Bp = s_B + b2 * BSZ + (kt * 16 + ocl) * BPITCH + cq * 7;
            float s = 0.f;
#pragma unroll
            for (int k = 0; k < 7; k++) {
                uint32_t v = Bp[k];
                __nv_bfloat162 hh = *(__nv_bfloat162*)&v;
                float2 f = __bfloat1622float2(hh);
                s += f.x + f.y;
            }
            csum += s;
        }

        __syncthreads();
    }

    float* dst = g_Cpart + ((size_t)band * 512 + kt * 128 + w * 16) * 64;
#pragma unroll
    for (int nt = 0; nt < 8; nt++) {
        *(float2*)&dst[(g)     * 64 + nt * 8 + 2 * t] = make_float2(c[nt][0], c[nt][1]);
        *(float2*)&dst[(g + 8) * 64 + nt * 8 + 2 * t] = make_float2(c[nt][2], c[nt][3]);
    }

    float* ydst = g_ytypart + (size_t)band * 4096;
    {
        const int col = w * 8 + 2 * t;
        *(float2*)&ydst[(kt * 16 + g) * 64 + col]     = make_float2(cy[0], cy[1]);
        *(float2*)&ydst[(kt * 16 + g + 8) * 64 + col] = make_float2(cy[2], cy[3]);
    }

    csum += __shfl_xor_sync(0xFFFFFFFFu, csum, 1);
    csum += __shfl_xor_sync(0xFFFFFFFFu, csum, 2);
    csum += __shfl_xor_sync(0xFFFFFFFFu, csum, 4);
    csum += __shfl_xor_sync(0xFFFFFFFFu, csum, 8);
    if (cq == 0) g_colpart[band * OCH + kt * 16 + ocl] = csum;
}

// ======================================================================
// K3a: reduce stage 1: 110 bands -> 5 groups of 22. grid (37, 5).
// ======================================================================
__global__ void k_reduce1()
{
    int e = blockIdx.x * 256 + threadIdx.x;
    int gg = blockIdx.y;
    if (e < 8192) {
        const float4* P = (const float4*)g_Cpart;
        float4 s = make_float4(0.f, 0.f, 0.f, 0.f);
#pragma unroll 11
        for (int b = 0; b < 22; b++) {
            float4 v = P[(size_t)(gg * 22 + b) * 8192 + e];
            s.x += v.x; s.y += v.y; s.z += v.z; s.w += v.w;
        }
        ((float4*)g_Cred)[gg * 8192 + e] = s;
    } else if (e < 9216) {
        int i = e - 8192;
        const float4* P = (const float4*)g_ytypart;
        float4 s = make_float4(0.f, 0.f, 0.f, 0.f);
#pragma unroll 11
        for (int b = 0; b < 22; b++) {
            float4 v = P[(size_t)(gg * 22 + b) * 1024 + i];
            s.x += v.x; s.y += v.y; s.z += v.z; s.w += v.w;
        }
        ((float4*)g_ytyred)[gg * 1024 + i] = s;
    }
}

// ======================================================================
// K3b: reduce stage 2 (+ exp_new / gfp). grid 37.
// ======================================================================
__global__ void k_reduce2(const float* __restrict__ exp_avg,
                          float* __restrict__ dout)
{
    int e = blockIdx.x * 256 + threadIdx.x;
    if (e < 8192) {
        const float4* P = (const float4*)g_Cred;
        float4 s = make_float4(0.f, 0.f, 0.f, 0.f);
#pragma unroll
        for (int gg = 0; gg < NG; gg++) {
            float4 v = P[gg * 8192 + e];
            s.x += v.x; s.y += v.y; s.z += v.z; s.w += v.w;
        }
        ((float4*)g_Cfin)[e] = s;
    } else if (e < 9216) {
        int i = e - 8192;
        const float4* P = (const float4*)g_ytyred;
        float4 s = make_float4(0.f, 0.f, 0.f, 0.f);
#pragma unroll
        for (int gg = 0; gg < NG; gg++) {
            float4 v = P[gg * 1024 + i];
            s.x += v.x; s.y += v.y; s.z += v.z; s.w += v.w;
        }
        ((float4*)g_ytyF)[i] = s;
    }

    if (blockIdx.x == 36) {
        __shared__ float sh[OCH];
        int t = threadIdx.x;
        if (t < OCH) {
            float cs = 0.f;
#pragma unroll 10
            for (int b = 0; b < MB2; b++) cs += g_colpart[b * OCH + t];
            float en = 0.99f * exp_avg[t] + (1.0f - 0.99f) * (cs / (float)NB);
            sh[t] = en;
            dout[OUT_OFF_EXP + t] = en;
        }
        __syncthreads();
        if (t < OCH) {
            float s = 0.f;
            for (int i = 0; i < OCH; i++) s += sh[i];
            float A = sh[t] / (s * (1.0f / (float)OCH));
            g_gfp[t] = 0.01f * tanhf(-0.01f * (A - 1.0f)) + 1.0f;
        }
    }
}

// ======================================================================
// K4: weight update.
// ======================================================================
__global__ void k_wupd(const float* __restrict__ W, float* __restrict__ dout)
{
    int idx = blockIdx.x * 256 + threadIdx.x;
    if (idx >= OCH * KTOT) return;
    int oc = idx / KTOT;
    int k = idx - oc * KTOT;
    float dot = 0.f;
#pragma unroll 8
    for (int b = 0; b < OCH; b++)
        dot += g_ytyF[oc * OCH + b] * W[b * KTOT + k];
    const float LRN = (float)(0.005 / 48400.0);
    float d = LRN * (g_Cfin[k * 64 + oc] - dot);
    float wn = fmaxf(W[idx] + d, 0.f);
    dout[OUT_OFF_W + idx] = wn * g_gfp[oc];
}

// ======================================================================
extern "C" void kernel_launch(void* const* d_in, const int* in_sizes, int n_in,
                              void* d_out, int out_size)
{
    const float* x  = (const float*)d_in[0];
    const float* W  = (const float*)d_in[1];
    const float* ea = (const float*)d_in[2];
    float* dout = (float*)d_out;

    const int ytxf_smem = 2 * BSZ * 4;   // 59392 B
    cudaFuncSetAttribute(k_ytxf_mma,
                         cudaFuncAttributeMaxDynamicSharedMemorySize, ytxf_smem);

    k_cvt_x<<<(XSZ + 255) / 256, 256>>>(x);
    k_cvt_w<<<(OCH * KTOT + OCH * 440 + 255) / 256, 256>>>(W);
    dim3 g1(2, 220);
    k_conv_mma<<<g1, 224>>>(dout);
    dim3 g2(MB2, 4);
    k_ytxf_mma<<<g2, 256, ytxf_smem>>>();
    dim3 g3(37, NG);
    k_reduce1<<<g3, 256>>>();
    k_reduce2<<<37, 256>>>(ea, dout);
    k_wupd<<<100, 256>>>(W, dout);
}